// round 12
// baseline (speedup 1.0000x reference)
#include <cuda_runtime.h>
#include <cuda_fp16.h>
#include <cstdint>
#include <math.h>

// ---------------- problem constants ----------------
#define B_SZ 16
#define H_SZ 8
#define L_SZ 1024
#define E_SZ 64
#define RS   512                 // floats between consecutive rows (H*E)

#define BM 128
#define BN 64
#define NT 16
#define THREADS 256

// ---------------- smem byte map (fp16 tiles, 128B swizzled rows) ------------
#define QO   0                       // 128 x 64 fp16 = 16 KB
#define KO(b) (16384 + (b) * 8192)   // 64 x 64 fp16, 3-stage ring
#define VO(b) (40960 + (b) * 8192)
#define SMEM_BYTES 65536

// precomputed tensors
__device__ __half g_kh[B_SZ * H_SZ * L_SZ * E_SZ];   // [bh][s][e] fp16
__device__ __half g_vh[B_SZ * H_SZ * L_SZ * E_SZ];
// g_wh[l][s] = fp16( softmax_s(wm[l][s]/softplus(tau[l])) * (1/8) * log2(e) )
__device__ __half g_wh[L_SZ * L_SZ];

// ---------------- helpers ----------------
__device__ __forceinline__ uint32_t smem_u32(const void* p) {
    uint32_t a;
    asm("{ .reg .u64 t; cvta.to.shared.u64 t, %1; cvt.u32.u64 %0, t; }" : "=r"(a) : "l"(p));
    return a;
}
// 128B-row XOR swizzle
__device__ __forceinline__ uint32_t swz(int r, int cb) {
    return (uint32_t)(r * 128 + (cb ^ ((r & 7) << 4)));
}

#define LDSM4(d0,d1,d2,d3,a) \
    asm volatile("ldmatrix.sync.aligned.m8n8.x4.shared.b16 {%0,%1,%2,%3}, [%4];" \
        : "=r"(d0),"=r"(d1),"=r"(d2),"=r"(d3) : "r"(a))
#define LDSM4T(d0,d1,d2,d3,a) \
    asm volatile("ldmatrix.sync.aligned.m8n8.x4.trans.shared.b16 {%0,%1,%2,%3}, [%4];" \
        : "=r"(d0),"=r"(d1),"=r"(d2),"=r"(d3) : "r"(a))
#define MMA16816(c, a0,a1,a2,a3, b0,b1) \
    asm volatile("mma.sync.aligned.m16n8k16.row.col.f32.f16.f16.f32 " \
        "{%0,%1,%2,%3},{%4,%5,%6,%7},{%8,%9},{%0,%1,%2,%3};" \
        : "+f"((c)[0]),"+f"((c)[1]),"+f"((c)[2]),"+f"((c)[3]) \
        : "r"(a0),"r"(a1),"r"(a2),"r"(a3),"r"(b0),"r"(b1))
#define CPA16(dst, src) \
    asm volatile("cp.async.cg.shared.global [%0], [%1], 16;" :: "r"(dst), "l"(src))
#define CPA_COMMIT() asm volatile("cp.async.commit_group;" ::: "memory")
#define CPA_WAIT0()  asm volatile("cp.async.wait_group 0;" ::: "memory")
#define CPA_WAIT1()  asm volatile("cp.async.wait_group 1;" ::: "memory")

// pack two fp32 -> half2 (lo = first arg)
#define PACK2F(out, lo, hi) \
    asm("cvt.rn.f16x2.f32 %0, %1, %2;" : "=r"(out) : "f"(hi), "f"(lo))
#define HMUL2(out, a, b) \
    asm("mul.rn.f16x2 %0, %1, %2;" : "=r"(out) : "r"(a), "r"(b))
#define EX2H2(out, a) \
    asm("ex2.approx.f16x2 %0, %1;" : "=r"(out) : "r"(a))

__device__ __forceinline__ uint2 pack4h(float4 x) {
    half2 h0 = __floats2half2_rn(x.x, x.y);
    half2 h1 = __floats2half2_rn(x.z, x.w);
    return make_uint2(*(uint32_t*)&h0, *(uint32_t*)&h1);
}

// ---------------- kernel 0: K/V fp32 -> fp16, bh-major ----------------
__global__ void kvprep_kernel(const float* __restrict__ k, const float* __restrict__ v) {
    int o = blockIdx.x * 256 + threadIdx.x;      // half4 index, 2^21 total
    int e4 = o & 15;
    int s  = (o >> 4) & 1023;
    int bh = o >> 14;
    int b = bh >> 3, h = bh & 7;
    size_t in = (((size_t)b * L_SZ + s) * H_SZ + h) * 16 + e4;   // float4 units
    ((uint2*)g_kh)[o] = pack4h(((const float4*)k)[in]);
    ((uint2*)g_vh)[o] = pack4h(((const float4*)v)[in]);
}

// ---------------- kernel 1: modulation weights (fp16 out) ----------------
__global__ void wprep_kernel(const float* __restrict__ wm, const float* __restrict__ tau) {
    __shared__ float red_m[8];
    __shared__ float red_s[8];
    const int row = blockIdx.x, tid = threadIdx.x;
    const int warp = tid >> 5, lane = tid & 31;

    float t = tau[row];
    float sp = (t > 20.f) ? t : log1pf(__expf(t));
    float inv = 1.f / sp;

    float4 x = reinterpret_cast<const float4*>(wm + (size_t)row * L_SZ)[tid];
    x.x *= inv; x.y *= inv; x.z *= inv; x.w *= inv;

    float mx = fmaxf(fmaxf(x.x, x.y), fmaxf(x.z, x.w));
    #pragma unroll
    for (int o = 16; o; o >>= 1) mx = fmaxf(mx, __shfl_xor_sync(0xffffffffu, mx, o));
    if (lane == 0) red_m[warp] = mx;
    __syncthreads();
    float M = red_m[0];
    #pragma unroll
    for (int i = 1; i < 8; i++) M = fmaxf(M, red_m[i]);

    float e0 = __expf(x.x - M), e1 = __expf(x.y - M);
    float e2 = __expf(x.z - M), e3 = __expf(x.w - M);
    float s = e0 + e1 + e2 + e3;
    #pragma unroll
    for (int o = 16; o; o >>= 1) s += __shfl_xor_sync(0xffffffffu, s, o);
    if (lane == 0) red_s[warp] = s;
    __syncthreads();
    float S = 0.f;
    #pragma unroll
    for (int i = 0; i < 8; i++) S += red_s[i];

    float f = 0.125f / S * 1.44269504089f;   // fold 1/sqrt(E) and log2(e)
    ((uint2*)g_wh)[row * (L_SZ / 4) + tid] =
        pack4h(make_float4(e0 * f, e1 * f, e2 * f, e3 * f));
}

// -- kernel 2: fp16 mma flash attention, h2 softmax, ones-MMA row sums ------
__global__ void __launch_bounds__(THREADS, 2)
flash_kernel(const float* __restrict__ q, float* __restrict__ out) {
    extern __shared__ char smem[];
    const uint32_t sb = smem_u32(smem);

    const int tid = threadIdx.x;
    const int warp = tid >> 5, lane = tid & 31;    // 8 M-warps, 16 rows each
    const int g = lane >> 2, t4 = lane & 3;
    const int l0 = blockIdx.x * BM;
    const int bh = blockIdx.y;

    const size_t base = (size_t)(bh >> 3) * (L_SZ * RS) + (size_t)(bh & 7) * E_SZ;
    const float* qb = q + base;
    float* ob = out + base;
    const __half* khb = g_kh + (size_t)bh * (L_SZ * E_SZ);
    const __half* vhb = g_vh + (size_t)bh * (L_SZ * E_SZ);
    const __half* whb = g_wh + (size_t)(l0 + 16 * warp + g) * L_SZ + 2 * t4;

    // chunk assignment for cp.async tile fills: 2 x 16B per thread per tile
    const int c0r = tid >> 3, c0c = (tid & 7) << 4;      // rows 0..31 / +32

    // ---- prologue: issue tiles 0 and 1, stage Q ----
    #pragma unroll
    for (int t = 0; t < 2; t++) {
        const int s0 = t * BN;
        CPA16(sb + KO(t) + swz(c0r, c0c), khb + (s0 + c0r) * 64 + (c0c >> 1));
        CPA16(sb + KO(t) + swz(c0r + 32, c0c), khb + (s0 + c0r + 32) * 64 + (c0c >> 1));
        CPA16(sb + VO(t) + swz(c0r, c0c), vhb + (s0 + c0r) * 64 + (c0c >> 1));
        CPA16(sb + VO(t) + swz(c0r + 32, c0c), vhb + (s0 + c0r + 32) * 64 + (c0c >> 1));
        CPA_COMMIT();
    }
    #pragma unroll
    for (int i = 0; i < 8; i++) {
        int e4 = i * THREADS + tid;              // 2048 float4
        int r = e4 >> 4, c = (e4 & 15) << 2;
        float4 x = *(const float4*)(qb + (size_t)(l0 + r) * RS + c);
        *(uint2*)(smem + QO + swz(r, c * 2)) = pack4h(x);
    }
    CPA_WAIT1();        // tile 0 landed
    __syncthreads();    // Q + tile 0 visible to all warps

    // ---- persistent Q fragments (rows 16*warp..+15, k=0..63): 16 regs ----
    uint32_t QA[4][4];
    #pragma unroll
    for (int kbk = 0; kbk < 4; kbk++)
        LDSM4(QA[kbk][0], QA[kbk][1], QA[kbk][2], QA[kbk][3],
              sb + QO + swz(16 * warp + (lane & 15), kbk * 32 + ((lane >> 4) << 4)));

    float O[8][4];
    #pragma unroll
    for (int nb = 0; nb < 8; nb++) {
        O[nb][0] = 0.f; O[nb][1] = 0.f; O[nb][2] = 0.f; O[nb][3] = 0.f;
    }
    float LSa[4] = {0.f, 0.f, 0.f, 0.f};     // row sums via ones-MMA
    const uint32_t ONESH2 = 0x3C003C00u;     // half2(1,1)

    for (int st = 0; st < NT; st++) {
        const int buf = st % 3;

        // issue cp.async for tile st+2 into its ring slot (read at st-1, freed)
        if (st + 2 < NT) {
            const int nb3 = (st + 2) % 3;
            const int s0n = (st + 2) * BN;
            CPA16(sb + KO(nb3) + swz(c0r, c0c), khb + (s0n + c0r) * 64 + (c0c >> 1));
            CPA16(sb + KO(nb3) + swz(c0r + 32, c0c), khb + (s0n + c0r + 32) * 64 + (c0c >> 1));
            CPA16(sb + VO(nb3) + swz(c0r, c0c), vhb + (s0n + c0r) * 64 + (c0c >> 1));
            CPA16(sb + VO(nb3) + swz(c0r + 32, c0c), vhb + (s0n + c0r + 32) * 64 + (c0c >> 1));
            CPA_COMMIT();
        }

        // prefetch w fragments (fp16 half2, L2-resident) — hidden behind S MMAs
        uint32_t wl0[8], wl1[8];
        {
            const __half* wr = whb + st * BN;
            #pragma unroll
            for (int nb = 0; nb < 8; nb++) {
                wl0[nb] = *(const uint32_t*)(wr + nb * 8);
                wl1[nb] = *(const uint32_t*)(wr + nb * 8 + 8 * L_SZ);
            }
        }

        // ---- S = Q K^T : 16 LDSM4 + 32 MMA (16 rows x 64 s-cols) ----
        float S[8][4];
        #pragma unroll
        for (int nb = 0; nb < 8; nb++) {
            S[nb][0] = 0.f; S[nb][1] = 0.f; S[nb][2] = 0.f; S[nb][3] = 0.f;
        }
        #pragma unroll
        for (int s16 = 0; s16 < 4; s16++) {
            #pragma unroll
            for (int kbk = 0; kbk < 4; kbk++) {
                uint32_t Kf0, Kf1, Kf2, Kf3;
                int rk = s16 * 16 + (lane & 7) + ((lane & 16) >> 1);
                int cbk = kbk * 32 + (((lane >> 3) & 1) << 4);
                LDSM4(Kf0, Kf1, Kf2, Kf3, sb + KO(buf) + swz(rk, cbk));
                MMA16816(S[2 * s16],     QA[kbk][0], QA[kbk][1], QA[kbk][2], QA[kbk][3], Kf0, Kf1);
                MMA16816(S[2 * s16 + 1], QA[kbk][0], QA[kbk][1], QA[kbk][2], QA[kbk][3], Kf2, Kf3);
            }
        }

        // ---- softmax in fp16x2: p = ex2(h2(s) * w_h2); |z|<<1 -> no max ----
        uint32_t P[4][4];
        #pragma unroll
        for (int nb = 0; nb < 8; nb++) {
            uint32_t s01, s23, z0, z1;
            PACK2F(s01, S[nb][0], S[nb][1]);
            PACK2F(s23, S[nb][2], S[nb][3]);
            HMUL2(z0, s01, wl0[nb]);
            HMUL2(z1, s23, wl1[nb]);
            EX2H2(P[nb >> 1][(nb & 1) * 2],     z0);
            EX2H2(P[nb >> 1][(nb & 1) * 2 + 1], z1);
        }

        // ---- row sums: LSa += P * ones (4 MMAs; exact sums of stored P) ----
        #pragma unroll
        for (int kb = 0; kb < 4; kb++)
            MMA16816(LSa, P[kb][0], P[kb][1], P[kb][2], P[kb][3], ONESH2, ONESH2);

        // ---- O += P V : 16 LDSM4T + 32 MMA (full k=64) ----
        #pragma unroll
        for (int kb = 0; kb < 4; kb++) {
            uint32_t Vf[4][4];
            #pragma unroll
            for (int n16 = 0; n16 < 4; n16++) {
                int rv = kb * 16 + (lane & 15);
                int cbv = n16 * 32 + ((lane >> 4) << 4);
                LDSM4T(Vf[n16][0], Vf[n16][1], Vf[n16][2], Vf[n16][3],
                       sb + VO(buf) + swz(rv, cbv));
            }
            #pragma unroll
            for (int nb = 0; nb < 8; nb++)
                MMA16816(O[nb], P[kb][0], P[kb][1], P[kb][2], P[kb][3],
                         Vf[nb >> 1][(nb & 1) * 2], Vf[nb >> 1][(nb & 1) * 2 + 1]);
        }

        // ensure tile st+1 landed; barrier frees this iter's ring slot
        if (st < NT - 1) {
            if (st + 2 < NT) CPA_WAIT1(); else CPA_WAIT0();
            __syncthreads();
        }
    }

    // ---- epilogue: scale by 1/rowsum (all n-cols of LSa identical) ----
    float inv0 = 1.f / LSa[0];
    float inv1 = 1.f / LSa[2];

    int r = l0 + 16 * warp + g;
    #pragma unroll
    for (int nb = 0; nb < 8; nb++) {
        int c = 8 * nb + 2 * t4;
        *(float2*)(ob + (size_t)r * RS + c) =
            make_float2(O[nb][0] * inv0, O[nb][1] * inv0);
        *(float2*)(ob + (size_t)(r + 8) * RS + c) =
            make_float2(O[nb][2] * inv1, O[nb][3] * inv1);
    }
}

// ---------------- launcher ----------------
extern "C" void kernel_launch(void* const* d_in, const int* in_sizes, int n_in,
                              void* d_out, int out_size) {
    const float* q   = (const float*)d_in[0];
    const float* k   = (const float*)d_in[1];
    const float* v   = (const float*)d_in[2];
    const float* wm  = (const float*)d_in[3];
    const float* tau = (const float*)d_in[4];
    // d_in[5] = attn_mask, unused (mask_flag=False)

    cudaFuncSetAttribute(flash_kernel, cudaFuncAttributeMaxDynamicSharedMemorySize, SMEM_BYTES);

    kvprep_kernel<<<(B_SZ * H_SZ * L_SZ * E_SZ / 4) / 256, 256>>>(k, v);
    wprep_kernel<<<L_SZ, 256>>>(wm, tau);

    dim3 grid(L_SZ / BM, B_SZ * H_SZ);
    flash_kernel<<<grid, THREADS, SMEM_BYTES>>>(q, (float*)d_out);
}